// round 14
// baseline (speedup 1.0000x reference)
#include <cuda_runtime.h>
#include <math.h>
#include <stdint.h>

#define B   128
#define L   500
#define H   512
#define LD  256
#define UD  128
#define V   33
#define H3  1536
#define NCTA 128
#define NT   512

// dynamic smem float offsets
#define SO_W     0        // 12x512 W_hh (r,z,n x 4 j)
#define SO_CATH  6144     // 4x512 cat_W h-half rows
#define SO_CATM  8192     // 4x128 catM rows
#define SO_MW4   8704     // 4x128 mem_W rows (own 4 j)
#define SO_MB4   9216     // 4 (+pad)
#define SO_OUTW  9232     // 4x34 (+pad)
#define SO_CC    9376     // 4x128 cc
#define SO_H4    9888     // 4x128 h_new own j
#define SO_SB    10400    // 16384: A staging double buffer / finish scratch
#define SO_SPART 26784    // 8192: 4 partial sets x (4 streams x 4 j x 128 b)
#define SO_SBB   34976    // 1664: B attention scratch
#define SO_SQS   36640    // 16384: B chunk staging, then qs staging
#define SO_ACQ   53024    // 512: accq[j][b]
#define SMEM_FLOATS 53536
#define SMEM_BYTES  (SMEM_FLOATS * 4)

#define PH_H   0
#define PH_Q   1
#define PH_PL  2
#define PH_TOK 3

// ---------------- device scratch ---------------------------------------------
__device__ __align__(16) float g_tbl[H3 * V];
__device__ __align__(16) float g_h[2][H * B];        // [j][b] ping-pong
__device__ __align__(16) float g_qs[UD * B];         // [d][b]
__device__ __align__(16) float g_plog[NCTA * V * B]; // [cta][v][b]
__device__ __align__(16) float g_pp[(size_t)NCTA * B * UD]; // [c][b][d]
__device__ __align__(16) float g_spp[NCTA * B];      // [c][b]
__device__ __align__(16) float g_catM[H * UD];
__device__ float g_catb2[H];
__device__ int g_tok[B];
__device__ __align__(128) unsigned g_flagsD[4][NCTA][8];

// ---------------- helpers ----------------------------------------------------
__device__ __forceinline__ float ldcg(const float* p) {
    float v; asm volatile("ld.global.cg.f32 %0, [%1];" : "=f"(v) : "l"(p)); return v;
}
__device__ __forceinline__ void stcg(float* p, float v) {
    asm volatile("st.global.cg.f32 [%0], %1;" :: "l"(p), "f"(v));
}
__device__ __forceinline__ void stcg4(float* p, float4 v) {
    asm volatile("st.global.cg.v4.f32 [%0], {%1,%2,%3,%4};"
                 :: "l"(p), "f"(v.x), "f"(v.y), "f"(v.z), "f"(v.w));
}
__device__ __forceinline__ float4 ldcg4(const float4* p) {
    float4 v;
    asm volatile("ld.global.cg.v4.f32 {%0,%1,%2,%3}, [%4];"
                 : "=f"(v.x), "=f"(v.y), "=f"(v.z), "=f"(v.w) : "l"(p));
    return v;
}
__device__ __forceinline__ int ldcg_i(const int* p) {
    int v; asm volatile("ld.global.cg.s32 %0, [%1];" : "=r"(v) : "l"(p)); return v;
}
__device__ __forceinline__ void stcg_i(int* p, int v) {
    asm volatile("st.global.cg.s32 [%0], %1;" :: "l"(p), "r"(v));
}
__device__ __forceinline__ void d_arrive(int ph, int cta, unsigned val) {
    asm volatile("st.release.gpu.global.u32 [%0], %1;"
                 :: "l"(&g_flagsD[ph][cta][0]), "r"(val) : "memory");
}
__device__ __forceinline__ void d_poll(int ph, int idx, unsigned val) {
    const unsigned* f = &g_flagsD[ph][idx][0];
    unsigned cur;
    do {
        asm volatile("ld.acquire.gpu.global.u32 %0, [%1];"
                     : "=r"(cur) : "l"(f) : "memory");
    } while ((int)(cur - val) < 0);
}
__device__ __forceinline__ void d_wait(int ph, int tid, unsigned val) {
    if (tid < NCTA) d_poll(ph, tid, val);
    __syncthreads();
}
#define BARA() asm volatile("bar.sync 2, 256;" ::: "memory")
#define BARB() asm volatile("bar.sync 1, 256;" ::: "memory")
__device__ __forceinline__ void cpa16(uint32_t dst, const void* src) {
    asm volatile("cp.async.cg.shared.global [%0], [%1], 16;" :: "r"(dst), "l"(src));
}
__device__ __forceinline__ void cpa_commit() { asm volatile("cp.async.commit_group;"); }
__device__ __forceinline__ void cpa_wait1() { asm volatile("cp.async.wait_group 1;"); }
__device__ __forceinline__ void cpa_wait0() { asm volatile("cp.async.wait_group 0;"); }
__device__ __forceinline__ float sigf(float x) { return 1.f / (1.f + expf(-x)); }

// ---------------- single merged prep kernel ----------------------------------
__global__ void prep_all(const float* __restrict__ embed,
                         const float* __restrict__ W_ih,
                         const float* __restrict__ b_ih,
                         const float* __restrict__ latent,
                         const float* __restrict__ hid_W,
                         const float* __restrict__ hid_b,
                         const float* __restrict__ cat_W,
                         const float* __restrict__ mem_W,
                         const float* __restrict__ mem_b,
                         const float* __restrict__ cat_b) {
    int blk = blockIdx.x, tx = threadIdx.x;
    if (blk < H3) {
        if (tx >= V) return;
        const float* wr = W_ih + (size_t)blk * H;
        const float* er = embed + (size_t)tx * H;
        float acc = b_ih[blk];
#pragma unroll 4
        for (int k = 0; k < H; ++k) acc += er[k] * wr[k];
        g_tbl[blk * V + tx] = acc;
    } else if (blk < H3 + H) {
        int j = blk - H3;
        const float* wr = hid_W + (size_t)j * LD;
        const float* lt = latent + (size_t)tx * LD;
        float acc = hid_b[j];
#pragma unroll 4
        for (int k = 0; k < LD; ++k) acc += lt[k] * wr[k];
        g_h[0][j * B + tx] = acc;
    } else if (blk < H3 + 2 * H) {
        int j = blk - H3 - H;
        const float* cw = cat_W + (size_t)j * (2 * H) + H;
        float acc = 0.f;
#pragma unroll 4
        for (int k = 0; k < H; ++k) acc += cw[k] * mem_W[k * UD + tx];
        g_catM[j * UD + tx] = acc;
        if (tx == 0) {
            float s = cat_b[j];
            for (int k = 0; k < H; ++k) s += cw[k] * mem_b[k];
            g_catb2[j] = s;
        }
    } else {
        if (tx < NCTA) {
#pragma unroll
            for (int p = 0; p < 4; ++p) g_flagsD[p][tx][0] = 0u;
            g_tok[tx] = 0;
        }
    }
}

// ---------------- main persistent decoder ------------------------------------
__global__ void __launch_bounds__(NT, 1)
decoder_kernel(const float* __restrict__ u,
               const float* __restrict__ W_hh,
               const float* __restrict__ b_hh,
               const float* __restrict__ mem_W,
               const float* __restrict__ mem_b,
               const float* __restrict__ cat_W,
               const float* __restrict__ out_W,
               const float* __restrict__ out_b,
               float* __restrict__ out)
{
    extern __shared__ float DS[];
    float* sW    = DS + SO_W;
    float* sCatH = DS + SO_CATH;
    float* sCatM = DS + SO_CATM;
    float* sMW4  = DS + SO_MW4;
    float* sMB4  = DS + SO_MB4;
    float* sOutW = DS + SO_OUTW;
    float* sCC   = DS + SO_CC;
    float* sH4   = DS + SO_H4;
    float* SB    = DS + SO_SB;
    float* SPART = DS + SO_SPART;
    float* SBB   = DS + SO_SBB;
    float* SQS   = DS + SO_SQS;
    float* sACQ  = DS + SO_ACQ;
    const uint32_t sbAddr  = (uint32_t)__cvta_generic_to_shared(SB);
    const uint32_t sqsAddr = (uint32_t)__cvta_generic_to_shared(SQS);

    const int tid = threadIdx.x;
    const int cta = blockIdx.x;
    const int jc  = cta * 4;

    // ---- persistent weight loads ----
    for (int i = tid; i < 6144; i += NT) {
        int r = i >> 9, k = i & 511;
        sW[i] = W_hh[(size_t)((r >> 2) * H + jc + (r & 3)) * H + k];
    }
    for (int i = tid; i < 2048; i += NT)
        sCatH[i] = cat_W[(size_t)(jc + (i >> 9)) * (2 * H) + (i & 511)];
    for (int i = tid; i < 512; i += NT)
        sCatM[i] = g_catM[(jc + (i >> 7)) * UD + (i & 127)];
    for (int i = tid; i < 512; i += NT)
        sMW4[i] = mem_W[(size_t)(jc + (i >> 7)) * UD + (i & 127)];
    if (tid < 4) sMB4[tid] = mem_b[jc + tid];
    for (int i = tid; i < 4 * V; i += NT) {
        int jl_ = i / V, v_ = i % V;
        sOutW[jl_ * 34 + v_] = out_W[(size_t)v_ * H + jc + jl_];
    }
    __syncthreads();

    // shared thread identifiers
    const int ta  = tid;
    const int kh  = (ta >> 7) & 1;      // k-half within chunk (valid both groups)
    const int jp  = (ta >> 6) & 1;      // j-pair
    const int bp2 = ta & 63;            // b-pair (GEMM phase)
    const int jlA = (ta >> 6) & 3;      // post-reduction j (A-group semantics)
    const int bp  = ta & 63;
    const int jA  = jc + jlA;
    const float bhr = b_hh[jA], bhz = b_hh[H + jA], bhn = b_hh[2 * H + jA];
    const float ccb = g_catb2[jA];
    // GEMM weight rows for this thread's 2 j's (j0=2jp, j1=2jp+1)
    const float* wR0 = sW + (0 * 4 + 2 * jp) * 512;
    const float* wR1 = wR0 + 512;
    const float* wZ0 = sW + (1 * 4 + 2 * jp) * 512;
    const float* wZ1 = wZ0 + 512;
    const float* wN0 = sW + (2 * 4 + 2 * jp) * 512;
    const float* wN1 = wN0 + 512;
    const float* wC0 = sCatH + 2 * jp * 512;
    const float* wC1 = wC0 + 512;
    const int tb = tid - 256;           // B-group index (valid tid>=256)

    // post-reduction accumulators (A-group, live across phases)
    float ar0, ar1, az0, az1, an0, an1, ac0, ac1;

    for (int t = 0; t <= L; ++t) {
        const float* hin = g_h[t & 1];
        float* hout = g_h[(t + 1) & 1];

        if (t > 0) d_wait(PH_H, tid, (unsigned)t);

        // ================= SPLIT: A (warps 0-7) ∥ B (warps 8-15) ============
        if (tid < 256) {
            // ---- A: GEMM chunks 0..5 (k 0..383), 2j x 2b x k-half ----------
            float acc[4][2][2];
#pragma unroll
            for (int s = 0; s < 4; ++s)
#pragma unroll
                for (int jj = 0; jj < 2; ++jj) { acc[s][jj][0] = 0.f; acc[s][jj][1] = 0.f; }
            {
                const float4* s0 = (const float4*)hin;
#pragma unroll
                for (int i = 0; i < 8; ++i) {
                    int idx = ta + i * 256;
                    cpa16(sbAddr + idx * 16, s0 + idx);
                }
                cpa_commit();
            }
#pragma unroll 1
            for (int c = 0; c < 6; ++c) {
                if (c + 1 < 6) {
                    const float4* s = (const float4*)(hin + (c + 1) * 8192);
                    uint32_t d0 = sbAddr + ((c + 1) & 1) * 32768;
#pragma unroll
                    for (int i = 0; i < 8; ++i) {
                        int idx = ta + i * 256;
                        cpa16(d0 + idx * 16, s + idx);
                    }
                    cpa_commit();
                    cpa_wait1();
                } else {
                    cpa_wait0();
                }
                BARA();
                const float* hc = SB + (c & 1) * 8192 + (kh * 32) * B;
                const int kb = c * 64 + kh * 32;
#pragma unroll
                for (int kk = 0; kk < 32; kk += 4) {
                    float4 r0 = *(const float4*)(wR0 + kb + kk);
                    float4 r1 = *(const float4*)(wR1 + kb + kk);
                    float4 z0 = *(const float4*)(wZ0 + kb + kk);
                    float4 z1 = *(const float4*)(wZ1 + kb + kk);
                    float4 n0 = *(const float4*)(wN0 + kb + kk);
                    float4 n1 = *(const float4*)(wN1 + kb + kk);
                    float4 c0 = *(const float4*)(wC0 + kb + kk);
                    float4 c1 = *(const float4*)(wC1 + kb + kk);
#pragma unroll
                    for (int q = 0; q < 4; ++q) {
                        float2 hv = *(const float2*)(hc + (kk + q) * B + bp2 * 2);
                        float w;
                        w = ((const float*)&r0)[q];
                        acc[0][0][0] += w * hv.x; acc[0][0][1] += w * hv.y;
                        w = ((const float*)&r1)[q];
                        acc[0][1][0] += w * hv.x; acc[0][1][1] += w * hv.y;
                        w = ((const float*)&z0)[q];
                        acc[1][0][0] += w * hv.x; acc[1][0][1] += w * hv.y;
                        w = ((const float*)&z1)[q];
                        acc[1][1][0] += w * hv.x; acc[1][1][1] += w * hv.y;
                        w = ((const float*)&n0)[q];
                        acc[2][0][0] += w * hv.x; acc[2][0][1] += w * hv.y;
                        w = ((const float*)&n1)[q];
                        acc[2][1][0] += w * hv.x; acc[2][1][1] += w * hv.y;
                        w = ((const float*)&c0)[q];
                        acc[3][0][0] += w * hv.x; acc[3][0][1] += w * hv.y;
                        w = ((const float*)&c1)[q];
                        acc[3][1][0] += w * hv.x; acc[3][1][1] += w * hv.y;
                    }
                }
                BARA();
            }
            // store partials to sets kh (0/1); gather happens after the join
#pragma unroll
            for (int s = 0; s < 4; ++s)
#pragma unroll
                for (int jj = 0; jj < 2; ++jj)
                    *(float2*)(SPART + ((kh * 4 + s) * 4 + 2 * jp + jj) * 128 + bp2 * 2)
                        = make_float2(acc[s][jj][0], acc[s][jj][1]);
        } else {
            // ---- B: stage chunks 6,7; attention; GEMM k 384..511; qs+accq --
            {
                const float4* s6 = (const float4*)(hin + 6 * 8192);
                const float4* s7 = (const float4*)(hin + 7 * 8192);
#pragma unroll
                for (int i = 0; i < 8; ++i) {
                    int idx = tb + i * 256;
                    cpa16(sqsAddr + idx * 16, s6 + idx);
                }
                cpa_commit();
#pragma unroll
                for (int i = 0; i < 8; ++i) {
                    int idx = tb + i * 256;
                    cpa16(sqsAddr + 32768 + idx * 16, s7 + idx);
                }
                cpa_commit();
            }
            if (t >= 1) {
                // ---- attention for b=cta, producing qs(t-1) ----------------
                const int b = cta;
                {   // p[d] = sum_c pp[c][b][d] over 128 c (2 halves)
                    int d = tb & 127, half = tb >> 7;
                    float acc = 0.f;
                    const float* src = &g_pp[((size_t)(half * 64) * B + b) * UD + d];
#pragma unroll 8
                    for (int i = 0; i < 64; ++i)
                        acc += ldcg(src + (size_t)i * B * UD);
                    SBB[half * 128 + d] = acc;
                }
                if (tb < 32) {  // sbias
                    float s = 0.f;
#pragma unroll
                    for (int k = 0; k < 4; ++k)
                        s += ldcg(&g_spp[(tb * 4 + k) * B + b]);
#pragma unroll
                    for (int o = 16; o > 0; o >>= 1) s += __shfl_xor_sync(~0u, s, o);
                    if (tb == 0) SBB[384] = s;
                }
                BARB();
                if (tb < 128) SBB[256 + tb] = SBB[tb] + SBB[128 + tb];
                BARB();
                const float sbias = SBB[384];
                const int lane = tb & 31, wb = tb >> 5;   // wb 0..7
                float4 pv = *(const float4*)(SBB + 256 + lane * 4);
                const float* ub = u + (size_t)b * (L * UD) + lane * 4;
                float m0 = -1e30f, Z0 = 0.f, m1 = -1e30f, Z1 = 0.f;
                float4 q0 = {0, 0, 0, 0}, q1 = {0, 0, 0, 0};
                float4 nu0 = ldcg4((const float4*)(ub + (size_t)wb * UD));
                float4 nu1 = ldcg4((const float4*)(ub + (size_t)(wb + 8) * UD));
#pragma unroll 1
                for (int l0 = wb; l0 < L; l0 += 16) {
                    float4 u0 = nu0, u1 = nu1;
                    int l1 = l0 + 8;
                    int n0 = l0 + 16, n1 = l0 + 24;
                    if (n0 < L) {
                        nu0 = ldcg4((const float4*)(ub + (size_t)n0 * UD));
                        nu1 = (n1 < L) ? ldcg4((const float4*)(ub + (size_t)n1 * UD))
                                       : make_float4(0, 0, 0, 0);
                    }
                    float s0v = u0.x * pv.x + u0.y * pv.y + u0.z * pv.z + u0.w * pv.w;
                    float s1v = u1.x * pv.x + u1.y * pv.y + u1.z * pv.z + u1.w * pv.w;
#pragma unroll
                    for (int o = 16; o > 0; o >>= 1) {
                        s0v += __shfl_xor_sync(~0u, s0v, o);
                        s1v += __shfl_xor_sync(~0u, s1v, o);
                    }
                    s0v += sbias; s1v += sbias;
                    if (s0v > m0) {
                        float sc = expf(m0 - s0v);
                        Z0 = Z0 * sc + 1.f;
                        q0.x = q0.x * sc + u0.x; q0.y = q0.y * sc + u0.y;
                        q0.z = q0.z * sc + u0.z; q0.w = q0.w * sc + u0.w;
                        m0 = s0v;
                    } else {
                        float wt = expf(s0v - m0);
                        Z0 += wt;
                        q0.x += wt * u0.x; q0.y += wt * u0.y;
                        q0.z += wt * u0.z; q0.w += wt * u0.w;
                    }
                    if (l1 < L) {
                        if (s1v > m1) {
                            float sc = expf(m1 - s1v);
                            Z1 = Z1 * sc + 1.f;
                            q1.x = q1.x * sc + u1.x; q1.y = q1.y * sc + u1.y;
                            q1.z = q1.z * sc + u1.z; q1.w = q1.w * sc + u1.w;
                            m1 = s1v;
                        } else {
                            float wt = expf(s1v - m1);
                            Z1 += wt;
                            q1.x += wt * u1.x; q1.y += wt * u1.y;
                            q1.z += wt * u1.z; q1.w += wt * u1.w;
                        }
                    }
                }
                {
                    float mn = fmaxf(m0, m1);
                    float sc0 = expf(m0 - mn), sc1 = expf(m1 - mn);
                    Z0 = Z0 * sc0 + Z1 * sc1;
                    q0.x = q0.x * sc0 + q1.x * sc1; q0.y = q0.y * sc0 + q1.y * sc1;
                    q0.z = q0.z * sc0 + q1.z * sc1; q0.w = q0.w * sc0 + q1.w * sc1;
                    m0 = mn;
                }
                *(float4*)(SBB + 512 + wb * 128 + lane * 4) = q0;
                if (lane == 0) { SBB[400 + wb] = m0; SBB[408 + wb] = Z0; }
                BARB();
                if (tb == 0) {
                    float M = SBB[400];
                    for (int i = 1; i < 8; ++i) M = fmaxf(M, SBB[400 + i]);
                    float Zt = 0.f;
#pragma unroll
                    for (int i = 0; i < 8; ++i) {
                        float e = expf(SBB[400 + i] - M);
                        SBB[416 + i] = e;
                        Zt += e * SBB[408 + i];
                    }
                    SBB[424] = 1.f / Zt;
                }
                BARB();
                if (tb < 128) {
                    float acc = 0.f;
#pragma unroll
                    for (int i = 0; i < 8; ++i)
                        acc += SBB[416 + i] * SBB[512 + i * 128 + tb];
                    stcg(&g_qs[tb * B + b], acc * SBB[424]);
                }
                BARB();
                if (tb == 0) d_arrive(PH_Q, cta, (unsigned)t);
            }
            // ---- B GEMM: chunks 6,7 ----
            cpa_wait0();
            BARB();
            {
                float accB[4][2][2];
#pragma unroll
                for (int s = 0; s < 4; ++s)
#pragma unroll
                    for (int jj = 0; jj < 2; ++jj) { accB[s][jj][0] = 0.f; accB[s][jj][1] = 0.f; }
#pragma unroll
                for (int c = 0; c < 2; ++c) {
                    const float* hc = SQS + c * 8192 + (kh * 32) * B;
                    const int kb = (6 + c) * 64 + kh * 32;
#pragma unroll
                    for (int kk = 0; kk < 32; kk += 4) {
                        float4 r0 = *(const float4*)(wR0 + kb + kk);
                        float4 r1 = *(const float4*)(wR1 + kb + kk);
                        float4 z0 = *(const float4*)(wZ0 + kb + kk);
                        float4 z1 = *(const float4*)(wZ1 + kb + kk);
                        float4 n0 = *(const float4*)(wN0 + kb + kk);
                        float4 n1 = *(const float4*)(wN1 + kb + kk);
                        float4 c0 = *(const float4*)(wC0 + kb + kk);
                        float4 c1 = *(const float4*)(wC1 + kb + kk);
#pragma unroll
                        for (int q = 0; q < 4; ++q) {
                            float2 hv = *(const float2*)(hc + (kk + q) * B + bp2 * 2);
                            float w;
                            w = ((const float*)&r0)[q];
                            accB[0][0][0] += w * hv.x; accB[0][0][1] += w * hv.y;
                            w = ((const float*)&r1)[q];
                            accB[0][1][0] += w * hv.x; accB[0][1][1] += w * hv.y;
                            w = ((const float*)&z0)[q];
                            accB[1][0][0] += w * hv.x; accB[1][0][1] += w * hv.y;
                            w = ((const float*)&z1)[q];
                            accB[1][1][0] += w * hv.x; accB[1][1][1] += w * hv.y;
                            w = ((const float*)&n0)[q];
                            accB[2][0][0] += w * hv.x; accB[2][0][1] += w * hv.y;
                            w = ((const float*)&n1)[q];
                            accB[2][1][0] += w * hv.x; accB[2][1][1] += w * hv.y;
                            w = ((const float*)&c0)[q];
                            accB[3][0][0] += w * hv.x; accB[3][0][1] += w * hv.y;
                            w = ((const float*)&c1)[q];
                            accB[3][1][0] += w * hv.x; accB[3][1][1] += w * hv.y;
                        }
                    }
                }
#pragma unroll
                for (int s = 0; s < 4; ++s)
#pragma unroll
                    for (int jj = 0; jj < 2; ++jj)
                        *(float2*)(SPART + (((2 + kh) * 4 + s) * 4 + 2 * jp + jj) * 128 + bp2 * 2)
                            = make_float2(accB[s][jj][0], accB[s][jj][1]);
            }
            // ---- Q-wait (group-local, mostly free), stage qs, compute accq --
            if (t >= 1) {
                if (tb < NCTA) d_poll(PH_Q, tb, (unsigned)t);
                BARB();   // also orders: all B threads done reading SQS chunks
                {
                    const float4* s = (const float4*)g_qs;
#pragma unroll
                    for (int i = 0; i < 16; ++i) {
                        int idx = tb + i * 256;
                        cpa16(sqsAddr + idx * 16, s + idx);
                    }
                    cpa_commit();
                    cpa_wait0();
                }
                BARB();
                {
                    int bq = tb & 127;
                    const float* cm0 = sCatM + (2 * kh) * 128;
                    const float* cm1 = cm0 + 128;
                    float a0 = 0.f, a1 = 0.f;
#pragma unroll 8
                    for (int d = 0; d < 128; ++d) {
                        float qv = SQS[d * 128 + bq];
                        a0 += cm0[d] * qv;
                        a1 += cm1[d] * qv;
                    }
                    sACQ[(2 * kh) * 128 + bq] = a0;
                    sACQ[(2 * kh + 1) * 128 + bq] = a1;
                }
            }
        }
        __syncthreads();   // join A and B

        // ---- gather partials (4 sets) into R10-layout registers ----
        if (tid < 256) {
            ar0 = ar1 = az0 = az1 = an0 = an1 = ac0 = ac1 = 0.f;
#pragma unroll
            for (int set = 0; set < 4; ++set) {
                float2 v;
                v = *(const float2*)(SPART + ((set * 4 + 0) * 4 + jlA) * 128 + bp * 2);
                ar0 += v.x; ar1 += v.y;
                v = *(const float2*)(SPART + ((set * 4 + 1) * 4 + jlA) * 128 + bp * 2);
                az0 += v.x; az1 += v.y;
                v = *(const float2*)(SPART + ((set * 4 + 2) * 4 + jlA) * 128 + bp * 2);
                an0 += v.x; an1 += v.y;
                v = *(const float2*)(SPART + ((set * 4 + 3) * 4 + jlA) * 128 + bp * 2);
                ac0 += v.x; ac1 += v.y;
            }
        }

        // ================= finish step t-1 ==================================
        if (t > 0) {
            if (tid < 256) {   // cc for b-pair: ac + accq (precomputed by B)
                float a0 = sACQ[jlA * 128 + bp * 2];
                float a1 = sACQ[jlA * 128 + bp * 2 + 1];
                sCC[jlA * 128 + bp * 2]     = tanhf(ac0 + a0 + ccb);
                sCC[jlA * 128 + bp * 2 + 1] = tanhf(ac1 + a1 + ccb);
            }
            __syncthreads();
            {   // partial logits over own 4 j's, all b
                int vg = tid >> 7, b2 = tid & 127;
#pragma unroll
                for (int i = 0; i < 9; ++i) {
                    int v = vg + 4 * i;
                    if (v < V) {
                        float a = sOutW[v] * sCC[b2]
                                + sOutW[34 + v] * sCC[128 + b2]
                                + sOutW[68 + v] * sCC[256 + b2]
                                + sOutW[102 + v] * sCC[384 + b2];
                        stcg(&g_plog[((size_t)cta * V + v) * B + b2], a);
                    }
                }
            }
            __syncthreads();
            if (tid == 0) d_arrive(PH_PL, cta, (unsigned)t);
            d_wait(PH_PL, tid, (unsigned)t);
            {   // reduce logits for b=cta, emit column t-1, argmax
                const int b = cta;
                int cg = tid >> 6, v = tid & 63;
                if (v < V) {
                    float acc = 0.f;
#pragma unroll
                    for (int i = 0; i < 16; ++i)
                        acc += ldcg(&g_plog[((size_t)(cg * 16 + i) * V + v) * B + b]);
                    SB[4800 + cg * 64 + v] = acc;
                }
                __syncthreads();
                if (tid < V) {
                    float lg = out_b[tid];
#pragma unroll
                    for (int g = 0; g < 8; ++g) lg += SB[4800 + g * 64 + tid];
                    out[((size_t)b * V + tid) * L + (t - 1)] = lg;
                    SB[5400 + tid] = lg;
                }
                __syncthreads();
                if (t < L && tid == 0) {
                    float best = SB[5400];
                    int bi = 0;
                    for (int v2 = 1; v2 < V; ++v2) {
                        float lv = SB[5400 + v2];
                        if (lv > best) { best = lv; bi = v2; }
                    }
                    stcg_i(&g_tok[b], bi);
                    d_arrive(PH_TOK, cta, (unsigned)t);
                }
                __syncthreads();   // protect SB[5400..] until argmax done
            }
        }

        // ================= epilogue: h state + p-partials ===================
        if (t < L) {
            if (t > 0) d_wait(PH_TOK, tid, (unsigned)t);
            if (tid < 256) {
                int b0 = bp * 2, b1 = b0 + 1;
                int tk0 = (t == 0) ? 0 : ldcg_i(&g_tok[b0]);
                int tk1 = (t == 0) ? 0 : ldcg_i(&g_tok[b1]);
                float hs0 = ldcg(&hin[jA * B + b0]);
                float hs1 = ldcg(&hin[jA * B + b1]);
                float r0 = sigf(g_tbl[jA * V + tk0] + ar0 + bhr);
                float z0 = sigf(g_tbl[(H + jA) * V + tk0] + az0 + bhz);
                float n0 = tanhf(g_tbl[(2 * H + jA) * V + tk0] + r0 * (an0 + bhn));
                float h0 = (1.f - z0) * n0 + z0 * hs0;
                float r1 = sigf(g_tbl[jA * V + tk1] + ar1 + bhr);
                float z1 = sigf(g_tbl[(H + jA) * V + tk1] + az1 + bhz);
                float n1 = tanhf(g_tbl[(2 * H + jA) * V + tk1] + r1 * (an1 + bhn));
                float h1 = (1.f - z1) * n1 + z1 * hs1;
                stcg(&hout[jA * B + b0], h0);
                stcg(&hout[jA * B + b1], h1);
                sH4[jlA * 128 + b0] = h0;
                sH4[jlA * 128 + b1] = h1;
            }
            __syncthreads();
            {   // p partials: pp[cta][b][d] = sum_jl mW4[jl][d]*h4[jl][b]
                int b2 = tid >> 2, dq = (tid & 3) * 32;
                float h0 = sH4[b2], h1 = sH4[128 + b2];
                float h2 = sH4[256 + b2], h3 = sH4[384 + b2];
                float* dst = &g_pp[((size_t)cta * B + b2) * UD + dq];
#pragma unroll
                for (int dd = 0; dd < 32; dd += 4) {
                    float4 w0 = *(const float4*)(sMW4 + dq + dd);
                    float4 w1 = *(const float4*)(sMW4 + 128 + dq + dd);
                    float4 w2 = *(const float4*)(sMW4 + 256 + dq + dd);
                    float4 w3 = *(const float4*)(sMW4 + 384 + dq + dd);
                    float4 rv;
                    rv.x = w0.x * h0 + w1.x * h1 + w2.x * h2 + w3.x * h3;
                    rv.y = w0.y * h0 + w1.y * h1 + w2.y * h2 + w3.y * h3;
                    rv.z = w0.z * h0 + w1.z * h1 + w2.z * h2 + w3.z * h3;
                    rv.w = w0.w * h0 + w1.w * h1 + w2.w * h2 + w3.w * h3;
                    stcg4(dst + dd, rv);
                }
            }
            if (tid < 128) {
                float s = sMB4[0] * sH4[tid] + sMB4[1] * sH4[128 + tid]
                        + sMB4[2] * sH4[256 + tid] + sMB4[3] * sH4[384 + tid];
                stcg(&g_spp[cta * B + tid], s);
            }
            __syncthreads();
            if (tid == 0) d_arrive(PH_H, cta, (unsigned)(t + 1));
        }
    }
}

// ---------------- launch -----------------------------------------------------
extern "C" void kernel_launch(void* const* d_in, const int* in_sizes, int n_in,
                              void* d_out, int out_size) {
    const float* latent = (const float*)d_in[0];
    const float* u      = (const float*)d_in[1];
    const float* embed  = (const float*)d_in[3];
    const float* hid_W  = (const float*)d_in[4];
    const float* hid_b  = (const float*)d_in[5];
    const float* mem_W  = (const float*)d_in[6];
    const float* mem_b  = (const float*)d_in[7];
    const float* W_ih   = (const float*)d_in[8];
    const float* W_hh   = (const float*)d_in[9];
    const float* b_ih   = (const float*)d_in[10];
    const float* b_hh   = (const float*)d_in[11];
    const float* cat_W  = (const float*)d_in[12];
    const float* cat_b  = (const float*)d_in[13];
    const float* out_W  = (const float*)d_in[14];
    const float* out_b  = (const float*)d_in[15];
    float* out = (float*)d_out;

    cudaFuncSetAttribute(decoder_kernel,
                         cudaFuncAttributeMaxDynamicSharedMemorySize, SMEM_BYTES);

    prep_all<<<H3 + 2 * H + 1, 128>>>(embed, W_ih, b_ih, latent, hid_W, hid_b,
                                      cat_W, mem_W, mem_b, cat_b);
    decoder_kernel<<<NCTA, NT, SMEM_BYTES>>>(u, W_hh, b_hh, mem_W, mem_b,
                                             cat_W, out_W, out_b, out);
}

// round 15
// speedup vs baseline: 1.0600x; 1.0600x over previous
#include <cuda_runtime.h>
#include <math.h>
#include <stdint.h>

#define B   128
#define L   500
#define H   512
#define LD  256
#define UD  128
#define V   33
#define H3  1536
#define NCTA 128
#define NT   512

// dynamic smem float offsets (R12 layout)
#define SO_W     0        // 12x512 W_hh (r,z,n x 4 j)
#define SO_CATH  6144     // 4x512 cat_W h-half rows
#define SO_CATM  8192     // 4x128 catM rows
#define SO_MW4   8704     // 4x128 mem_W rows (own 4 j)
#define SO_MB4   9216     // 4 (+pad)
#define SO_OUTW  9232     // 4x34 (+pad)
#define SO_CC    9376     // 4x128 cc
#define SO_H4    9888     // 4x128 h_new own j
#define SO_SB    10400    // 16384: A staging double buffer / finish scratch
#define SO_SBB   26784    // 1664: B-group scratch
#define SMEM_FLOATS 28448
#define SMEM_BYTES  (SMEM_FLOATS * 4)

#define PH_H   0
#define PH_Q   1
#define PH_PL  2
#define PH_TOK 3
#define PH_P   4

// ---------------- device scratch ---------------------------------------------
__device__ __align__(16) float g_tbl[H3 * V];
__device__ __align__(16) float g_h[2][H * B];        // [j][b] ping-pong
__device__ __align__(16) float g_qs[UD * B];         // [d][b]
__device__ __align__(16) float g_plog[NCTA * V * B]; // [cta][v][b]
__device__ __align__(16) float g_pp[(size_t)NCTA * B * UD]; // [c][b][d]
__device__ __align__(16) float g_spp[NCTA * B];      // [c][b]
__device__ __align__(16) float g_catM[H * UD];
__device__ float g_catb2[H];
__device__ int g_tok[B];
__device__ __align__(128) unsigned g_flagsD[5][NCTA][8];

// ---------------- helpers ----------------------------------------------------
__device__ __forceinline__ float ldcg(const float* p) {
    float v; asm volatile("ld.global.cg.f32 %0, [%1];" : "=f"(v) : "l"(p)); return v;
}
__device__ __forceinline__ void stcg(float* p, float v) {
    asm volatile("st.global.cg.f32 [%0], %1;" :: "l"(p), "f"(v));
}
__device__ __forceinline__ void stcg4(float* p, float4 v) {
    asm volatile("st.global.cg.v4.f32 [%0], {%1,%2,%3,%4};"
                 :: "l"(p), "f"(v.x), "f"(v.y), "f"(v.z), "f"(v.w));
}
__device__ __forceinline__ float4 ldcg4(const float4* p) {
    float4 v;
    asm volatile("ld.global.cg.v4.f32 {%0,%1,%2,%3}, [%4];"
                 : "=f"(v.x), "=f"(v.y), "=f"(v.z), "=f"(v.w) : "l"(p));
    return v;
}
__device__ __forceinline__ int ldcg_i(const int* p) {
    int v; asm volatile("ld.global.cg.s32 %0, [%1];" : "=r"(v) : "l"(p)); return v;
}
__device__ __forceinline__ void stcg_i(int* p, int v) {
    asm volatile("st.global.cg.s32 [%0], %1;" :: "l"(p), "r"(v));
}
__device__ __forceinline__ void d_arrive(int ph, int cta, unsigned val) {
    asm volatile("st.release.gpu.global.u32 [%0], %1;"
                 :: "l"(&g_flagsD[ph][cta][0]), "r"(val) : "memory");
}
__device__ __forceinline__ void d_poll(int ph, int idx, unsigned val) {
    const unsigned* f = &g_flagsD[ph][idx][0];
    unsigned cur;
    do {
        asm volatile("ld.acquire.gpu.global.u32 %0, [%1];"
                     : "=r"(cur) : "l"(f) : "memory");
    } while ((int)(cur - val) < 0);
}
__device__ __forceinline__ void d_wait(int ph, int tid, unsigned val) {
    if (tid < NCTA) d_poll(ph, tid, val);
    __syncthreads();
}
#define BARA() asm volatile("bar.sync 2, 256;" ::: "memory")
#define BARB() asm volatile("bar.sync 1, 256;" ::: "memory")
__device__ __forceinline__ void cpa16(uint32_t dst, const void* src) {
    asm volatile("cp.async.cg.shared.global [%0], [%1], 16;" :: "r"(dst), "l"(src));
}
__device__ __forceinline__ void cpa_commit() { asm volatile("cp.async.commit_group;"); }
__device__ __forceinline__ void cpa_wait1() { asm volatile("cp.async.wait_group 1;"); }
__device__ __forceinline__ void cpa_wait0() { asm volatile("cp.async.wait_group 0;"); }
__device__ __forceinline__ float sigf(float x) { return 1.f / (1.f + expf(-x)); }

// ---------------- single merged prep kernel ----------------------------------
__global__ void prep_all(const float* __restrict__ embed,
                         const float* __restrict__ W_ih,
                         const float* __restrict__ b_ih,
                         const float* __restrict__ latent,
                         const float* __restrict__ hid_W,
                         const float* __restrict__ hid_b,
                         const float* __restrict__ cat_W,
                         const float* __restrict__ mem_W,
                         const float* __restrict__ mem_b,
                         const float* __restrict__ cat_b) {
    int blk = blockIdx.x, tx = threadIdx.x;
    if (blk < H3) {
        if (tx >= V) return;
        const float* wr = W_ih + (size_t)blk * H;
        const float* er = embed + (size_t)tx * H;
        float acc = b_ih[blk];
#pragma unroll 4
        for (int k = 0; k < H; ++k) acc += er[k] * wr[k];
        g_tbl[blk * V + tx] = acc;
    } else if (blk < H3 + H) {
        int j = blk - H3;
        const float* wr = hid_W + (size_t)j * LD;
        const float* lt = latent + (size_t)tx * LD;
        float acc = hid_b[j];
#pragma unroll 4
        for (int k = 0; k < LD; ++k) acc += lt[k] * wr[k];
        g_h[0][j * B + tx] = acc;
    } else if (blk < H3 + 2 * H) {
        int j = blk - H3 - H;
        const float* cw = cat_W + (size_t)j * (2 * H) + H;
        float acc = 0.f;
#pragma unroll 4
        for (int k = 0; k < H; ++k) acc += cw[k] * mem_W[k * UD + tx];
        g_catM[j * UD + tx] = acc;
        if (tx == 0) {
            float s = cat_b[j];
            for (int k = 0; k < H; ++k) s += cw[k] * mem_b[k];
            g_catb2[j] = s;
        }
    } else {
        if (tx < NCTA) {
#pragma unroll
            for (int p = 0; p < 5; ++p) g_flagsD[p][tx][0] = 0u;
            g_tok[tx] = 0;
        }
    }
}

// ---------------- main persistent decoder ------------------------------------
__global__ void __launch_bounds__(NT, 1)
decoder_kernel(const float* __restrict__ u,
               const float* __restrict__ W_hh,
               const float* __restrict__ b_hh,
               const float* __restrict__ mem_W,
               const float* __restrict__ mem_b,
               const float* __restrict__ cat_W,
               const float* __restrict__ out_W,
               const float* __restrict__ out_b,
               float* __restrict__ out)
{
    extern __shared__ float DS[];
    float* sW    = DS + SO_W;
    float* sCatH = DS + SO_CATH;
    float* sCatM = DS + SO_CATM;
    float* sMW4  = DS + SO_MW4;
    float* sMB4  = DS + SO_MB4;
    float* sOutW = DS + SO_OUTW;
    float* sCC   = DS + SO_CC;
    float* sH4   = DS + SO_H4;
    float* SB    = DS + SO_SB;
    float* SBB   = DS + SO_SBB;
    const uint32_t sbAddr = (uint32_t)__cvta_generic_to_shared(SB);

    const int tid = threadIdx.x;
    const int cta = blockIdx.x;
    const int jc  = cta * 4;

    // ---- persistent weight loads ----
    for (int i = tid; i < 6144; i += NT) {
        int r = i >> 9, k = i & 511;
        sW[i] = W_hh[(size_t)((r >> 2) * H + jc + (r & 3)) * H + k];
    }
    for (int i = tid; i < 2048; i += NT)
        sCatH[i] = cat_W[(size_t)(jc + (i >> 9)) * (2 * H) + (i & 511)];
    for (int i = tid; i < 512; i += NT)
        sCatM[i] = g_catM[(jc + (i >> 7)) * UD + (i & 127)];
    for (int i = tid; i < 512; i += NT)
        sMW4[i] = mem_W[(size_t)(jc + (i >> 7)) * UD + (i & 127)];
    if (tid < 4) sMB4[tid] = mem_b[jc + tid];
    for (int i = tid; i < 4 * V; i += NT) {
        int jl_ = i / V, v_ = i % V;
        sOutW[jl_ * 34 + v_] = out_W[(size_t)v_ * H + jc + jl_];
    }
    __syncthreads();

    // thread identifiers
    const int ta  = tid;
    const int kh  = ta >> 7;            // k-half within chunk (A group)
    const int jp  = (ta >> 6) & 1;      // j-pair
    const int bp2 = ta & 63;            // b-pair (GEMM phase)
    const int jlA = (ta >> 6) & 3;      // post-reduction j
    const int bp  = ta & 63;
    const int jA  = jc + jlA;
    const float bhr = b_hh[jA], bhz = b_hh[H + jA], bhn = b_hh[2 * H + jA];
    const float ccb = g_catb2[jA];
    const float* wmp = sCatM + jlA * 128;
    const float* wR0 = sW + (0 * 4 + 2 * jp) * 512;
    const float* wR1 = wR0 + 512;
    const float* wZ0 = sW + (1 * 4 + 2 * jp) * 512;
    const float* wZ1 = wZ0 + 512;
    const float* wN0 = sW + (2 * 4 + 2 * jp) * 512;
    const float* wN1 = wN0 + 512;
    const float* wC0 = sCatH + 2 * jp * 512;
    const float* wC1 = wC0 + 512;
    const int tb = tid - 256;

    // live-across-phases registers
    float ar0, ar1, az0, az1, an0, an1, ac0, ac1, hs0, hs1;

    for (int t = 0; t <= L; ++t) {
        const float* hin = g_h[t & 1];
        float* hout = g_h[(t + 1) & 1];

        // ================= SPLIT: A (warps 0-7) ∥ B (warps 8-15) ============
        if (tid < 256) {
            // group-local wait: hout(t-1) stores visible (PH_H)
            if (t > 0 && ta < NCTA) d_poll(PH_H, ta, (unsigned)t);
            BARA();
            // ---- A: gates(t) + cch(t-1); 2j x 2b x k-half blocking ----------
            float acc[4][2][2];
#pragma unroll
            for (int s = 0; s < 4; ++s)
#pragma unroll
                for (int jj = 0; jj < 2; ++jj) { acc[s][jj][0] = 0.f; acc[s][jj][1] = 0.f; }
            hs0 = hs1 = 0.f;
            {
                const float4* s0 = (const float4*)hin;
#pragma unroll
                for (int i = 0; i < 8; ++i) {
                    int idx = ta + i * 256;
                    cpa16(sbAddr + idx * 16, s0 + idx);
                }
                cpa_commit();
            }
#pragma unroll 1
            for (int c = 0; c < 8; ++c) {
                if (c + 1 < 8) {
                    const float4* s = (const float4*)(hin + (c + 1) * 8192);
                    uint32_t d0 = sbAddr + ((c + 1) & 1) * 32768;
#pragma unroll
                    for (int i = 0; i < 8; ++i) {
                        int idx = ta + i * 256;
                        cpa16(d0 + idx * 16, s + idx);
                    }
                    cpa_commit();
                    cpa_wait1();
                } else {
                    cpa_wait0();
                }
                BARA();
                const float* hbase = SB + (c & 1) * 8192;
                const float* hc = hbase + (kh * 32) * B;
                const int kb = c * 64 + kh * 32;
#pragma unroll
                for (int kk = 0; kk < 32; kk += 4) {
                    float4 r0 = *(const float4*)(wR0 + kb + kk);
                    float4 r1 = *(const float4*)(wR1 + kb + kk);
                    float4 z0 = *(const float4*)(wZ0 + kb + kk);
                    float4 z1 = *(const float4*)(wZ1 + kb + kk);
                    float4 n0 = *(const float4*)(wN0 + kb + kk);
                    float4 n1 = *(const float4*)(wN1 + kb + kk);
                    float4 c0 = *(const float4*)(wC0 + kb + kk);
                    float4 c1 = *(const float4*)(wC1 + kb + kk);
#pragma unroll
                    for (int q = 0; q < 4; ++q) {
                        float2 hv = *(const float2*)(hc + (kk + q) * B + bp2 * 2);
                        float w;
                        w = ((const float*)&r0)[q];
                        acc[0][0][0] += w * hv.x; acc[0][0][1] += w * hv.y;
                        w = ((const float*)&r1)[q];
                        acc[0][1][0] += w * hv.x; acc[0][1][1] += w * hv.y;
                        w = ((const float*)&z0)[q];
                        acc[1][0][0] += w * hv.x; acc[1][0][1] += w * hv.y;
                        w = ((const float*)&z1)[q];
                        acc[1][1][0] += w * hv.x; acc[1][1][1] += w * hv.y;
                        w = ((const float*)&n0)[q];
                        acc[2][0][0] += w * hv.x; acc[2][0][1] += w * hv.y;
                        w = ((const float*)&n1)[q];
                        acc[2][1][0] += w * hv.x; acc[2][1][1] += w * hv.y;
                        w = ((const float*)&c0)[q];
                        acc[3][0][0] += w * hv.x; acc[3][0][1] += w * hv.y;
                        w = ((const float*)&c1)[q];
                        acc[3][1][0] += w * hv.x; acc[3][1][1] += w * hv.y;
                    }
                }
                if (c == (jA >> 6)) {   // harvest h_self for epilogue
                    float2 hv = *(const float2*)(hbase + (jA & 63) * B + bp * 2);
                    hs0 = hv.x; hs1 = hv.y;
                }
                BARA();
            }
            // ---- k-half reduction: partials -> SMEM -> R10-layout registers -
#pragma unroll
            for (int s = 0; s < 4; ++s)
#pragma unroll
                for (int jj = 0; jj < 2; ++jj)
                    *(float2*)(SB + ((kh * 4 + s) * 4 + 2 * jp + jj) * 128 + bp2 * 2)
                        = make_float2(acc[s][jj][0], acc[s][jj][1]);
            BARA();
            {
                float2 v0, v1;
                v0 = *(const float2*)(SB + ((0 * 4 + 0) * 4 + jlA) * 128 + bp * 2);
                v1 = *(const float2*)(SB + ((1 * 4 + 0) * 4 + jlA) * 128 + bp * 2);
                ar0 = v0.x + v1.x; ar1 = v0.y + v1.y;
                v0 = *(const float2*)(SB + ((0 * 4 + 1) * 4 + jlA) * 128 + bp * 2);
                v1 = *(const float2*)(SB + ((1 * 4 + 1) * 4 + jlA) * 128 + bp * 2);
                az0 = v0.x + v1.x; az1 = v0.y + v1.y;
                v0 = *(const float2*)(SB + ((0 * 4 + 2) * 4 + jlA) * 128 + bp * 2);
                v1 = *(const float2*)(SB + ((1 * 4 + 2) * 4 + jlA) * 128 + bp * 2);
                an0 = v0.x + v1.x; an1 = v0.y + v1.y;
                v0 = *(const float2*)(SB + ((0 * 4 + 3) * 4 + jlA) * 128 + bp * 2);
                v1 = *(const float2*)(SB + ((1 * 4 + 3) * 4 + jlA) * 128 + bp * 2);
                ac0 = v0.x + v1.x; ac1 = v0.y + v1.y;
            }
            BARA();   // partial area dead before SB reused
        } else {
            // group-local wait: p-partials visible (PH_P)
            if (t > 0 && tb < NCTA) d_poll(PH_P, tb, (unsigned)t);
            BARB();
            if (t >= 1) {
                // ---- B: attention for b=cta, producing qs(t-1) --------------
                const int b = cta;
                {
                    int d = tb & 127, half = tb >> 7;
                    float acc = 0.f;
                    const float* src = &g_pp[((size_t)(half * 64) * B + b) * UD + d];
#pragma unroll 8
                    for (int i = 0; i < 64; ++i)
                        acc += ldcg(src + (size_t)i * B * UD);
                    SBB[half * 128 + d] = acc;
                }
                if (tb < 32) {
                    float s = 0.f;
#pragma unroll
                    for (int k = 0; k < 4; ++k)
                        s += ldcg(&g_spp[(tb * 4 + k) * B + b]);
#pragma unroll
                    for (int o = 16; o > 0; o >>= 1) s += __shfl_xor_sync(~0u, s, o);
                    if (tb == 0) SBB[384] = s;
                }
                BARB();
                if (tb < 128) SBB[256 + tb] = SBB[tb] + SBB[128 + tb];
                BARB();
                const float sbias = SBB[384];
                const int lane = tb & 31, wb = tb >> 5;
                float4 pv = *(const float4*)(SBB + 256 + lane * 4);
                const float* ub = u + (size_t)b * (L * UD) + lane * 4;
                float m0 = -1e30f, Z0 = 0.f, m1 = -1e30f, Z1 = 0.f;
                float4 q0 = {0, 0, 0, 0}, q1 = {0, 0, 0, 0};
                float4 nu0 = ldcg4((const float4*)(ub + (size_t)wb * UD));
                float4 nu1 = ldcg4((const float4*)(ub + (size_t)(wb + 8) * UD));
#pragma unroll 1
                for (int l0 = wb; l0 < L; l0 += 16) {
                    float4 u0 = nu0, u1 = nu1;
                    int l1 = l0 + 8;
                    int n0 = l0 + 16, n1 = l0 + 24;
                    if (n0 < L) {
                        nu0 = ldcg4((const float4*)(ub + (size_t)n0 * UD));
                        nu1 = (n1 < L) ? ldcg4((const float4*)(ub + (size_t)n1 * UD))
                                       : make_float4(0, 0, 0, 0);
                    }
                    float s0v = u0.x * pv.x + u0.y * pv.y + u0.z * pv.z + u0.w * pv.w;
                    float s1v = u1.x * pv.x + u1.y * pv.y + u1.z * pv.z + u1.w * pv.w;
#pragma unroll
                    for (int o = 16; o > 0; o >>= 1) {
                        s0v += __shfl_xor_sync(~0u, s0v, o);
                        s1v += __shfl_xor_sync(~0u, s1v, o);
                    }
                    s0v += sbias; s1v += sbias;
                    if (s0v > m0) {
                        float sc = expf(m0 - s0v);
                        Z0 = Z0 * sc + 1.f;
                        q0.x = q0.x * sc + u0.x; q0.y = q0.y * sc + u0.y;
                        q0.z = q0.z * sc + u0.z; q0.w = q0.w * sc + u0.w;
                        m0 = s0v;
                    } else {
                        float wt = expf(s0v - m0);
                        Z0 += wt;
                        q0.x += wt * u0.x; q0.y += wt * u0.y;
                        q0.z += wt * u0.z; q0.w += wt * u0.w;
                    }
                    if (l1 < L) {
                        if (s1v > m1) {
                            float sc = expf(m1 - s1v);
                            Z1 = Z1 * sc + 1.f;
                            q1.x = q1.x * sc + u1.x; q1.y = q1.y * sc + u1.y;
                            q1.z = q1.z * sc + u1.z; q1.w = q1.w * sc + u1.w;
                            m1 = s1v;
                        } else {
                            float wt = expf(s1v - m1);
                            Z1 += wt;
                            q1.x += wt * u1.x; q1.y += wt * u1.y;
                            q1.z += wt * u1.z; q1.w += wt * u1.w;
                        }
                    }
                }
                {
                    float mn = fmaxf(m0, m1);
                    float sc0 = expf(m0 - mn), sc1 = expf(m1 - mn);
                    Z0 = Z0 * sc0 + Z1 * sc1;
                    q0.x = q0.x * sc0 + q1.x * sc1; q0.y = q0.y * sc0 + q1.y * sc1;
                    q0.z = q0.z * sc0 + q1.z * sc1; q0.w = q0.w * sc0 + q1.w * sc1;
                    m0 = mn;
                }
                *(float4*)(SBB + 512 + wb * 128 + lane * 4) = q0;
                if (lane == 0) { SBB[400 + wb] = m0; SBB[408 + wb] = Z0; }
                BARB();
                if (tb == 0) {
                    float M = SBB[400];
                    for (int i = 1; i < 8; ++i) M = fmaxf(M, SBB[400 + i]);
                    float Zt = 0.f;
#pragma unroll
                    for (int i = 0; i < 8; ++i) {
                        float e = expf(SBB[400 + i] - M);
                        SBB[416 + i] = e;
                        Zt += e * SBB[408 + i];
                    }
                    SBB[424] = 1.f / Zt;
                }
                BARB();
                if (tb < 128) {
                    float acc = 0.f;
#pragma unroll
                    for (int i = 0; i < 8; ++i)
                        acc += SBB[416 + i] * SBB[512 + i * 128 + tb];
                    stcg(&g_qs[tb * B + b], acc * SBB[424]);
                }
                BARB();
                if (tb == 0) d_arrive(PH_Q, cta, (unsigned)t);
            }
        }
        __syncthreads();   // join A and B

        // ================= finish step t-1 ==================================
        if (t > 0) {
            d_wait(PH_Q, tid, (unsigned)t);
            {   // stage FULL qs [d][b]
                const float4* s = (const float4*)g_qs;
                uint32_t d0 = sbAddr;
#pragma unroll
                for (int i = 0; i < 8; ++i) {
                    int idx = tid + i * 512;
                    cpa16(d0 + idx * 16, s + idx);
                }
                cpa_commit();
                cpa_wait0();
            }
            __syncthreads();
            if (tid < 256) {   // cc for b-pair
                float a0 = 0.f, a1 = 0.f;
#pragma unroll
                for (int d = 0; d < UD; d += 4) {
                    float4 w4 = *(const float4*)(wmp + d);
                    float2 v0 = *(const float2*)(SB + d * B + bp * 2);
                    float2 v1 = *(const float2*)(SB + (d + 1) * B + bp * 2);
                    float2 v2 = *(const float2*)(SB + (d + 2) * B + bp * 2);
                    float2 v3 = *(const float2*)(SB + (d + 3) * B + bp * 2);
                    a0 += w4.x * v0.x + w4.y * v1.x + w4.z * v2.x + w4.w * v3.x;
                    a1 += w4.x * v0.y + w4.y * v1.y + w4.z * v2.y + w4.w * v3.y;
                }
                sCC[jlA * 128 + bp * 2]     = tanhf(ac0 + a0 + ccb);
                sCC[jlA * 128 + bp * 2 + 1] = tanhf(ac1 + a1 + ccb);
            }
            __syncthreads();
            {   // partial logits over own 4 j's, all b
                int vg = tid >> 7, b2 = tid & 127;
#pragma unroll
                for (int i = 0; i < 9; ++i) {
                    int v = vg + 4 * i;
                    if (v < V) {
                        float a = sOutW[v] * sCC[b2]
                                + sOutW[34 + v] * sCC[128 + b2]
                                + sOutW[68 + v] * sCC[256 + b2]
                                + sOutW[102 + v] * sCC[384 + b2];
                        stcg(&g_plog[((size_t)cta * V + v) * B + b2], a);
                    }
                }
            }
            __syncthreads();
            if (tid == 0) d_arrive(PH_PL, cta, (unsigned)t);
            d_wait(PH_PL, tid, (unsigned)t);
            {   // reduce logits for b=cta, emit column t-1, warp-parallel argmax
                const int b = cta;
                int cg = tid >> 6, v = tid & 63;
                if (v < V) {
                    float acc = 0.f;
#pragma unroll
                    for (int i = 0; i < 16; ++i)
                        acc += ldcg(&g_plog[((size_t)(cg * 16 + i) * V + v) * B + b]);
                    SB[4800 + cg * 64 + v] = acc;
                }
                __syncthreads();
                if (tid < V) {
                    float lg = out_b[tid];
#pragma unroll
                    for (int g = 0; g < 8; ++g) lg += SB[4800 + g * 64 + tid];
                    out[((size_t)b * V + tid) * L + (t - 1)] = lg;
                    SB[5400 + tid] = lg;
                }
                __syncthreads();
                if (t < L && tid < 32) {   // butterfly argmax, first-occurrence
                    float v0 = (tid < V) ? SB[5400 + tid] : -3.4e38f;
                    int i0 = tid;
                    if (tid == 0) {
                        float v32 = SB[5400 + 32];
                        if (v32 > v0) { v0 = v32; i0 = 32; }
                    }
#pragma unroll
                    for (int o = 16; o > 0; o >>= 1) {
                        float ov = __shfl_xor_sync(~0u, v0, o);
                        int oi = __shfl_xor_sync(~0u, i0, o);
                        if (ov > v0 || (ov == v0 && oi < i0)) { v0 = ov; i0 = oi; }
                    }
                    if (tid == 0) {
                        stcg_i(&g_tok[b], i0);
                        d_arrive(PH_TOK, cta, (unsigned)t);
                    }
                }
                __syncthreads();   // protect SB[5400..] until argmax done
            }
        }

        // ================= epilogue: h state + p-partials ===================
        if (t < L) {
            if (t > 0) d_wait(PH_TOK, tid, (unsigned)t);
            if (tid < 256) {
                int b0 = bp * 2, b1 = b0 + 1;
                int tk0 = (t == 0) ? 0 : ldcg_i(&g_tok[b0]);
                int tk1 = (t == 0) ? 0 : ldcg_i(&g_tok[b1]);
                float r0 = sigf(g_tbl[jA * V + tk0] + ar0 + bhr);
                float z0 = sigf(g_tbl[(H + jA) * V + tk0] + az0 + bhz);
                float n0 = tanhf(g_tbl[(2 * H + jA) * V + tk0] + r0 * (an0 + bhn));
                float h0 = (1.f - z0) * n0 + z0 * hs0;
                float r1 = sigf(g_tbl[jA * V + tk1] + ar1 + bhr);
                float z1 = sigf(g_tbl[(H + jA) * V + tk1] + az1 + bhz);
                float n1 = tanhf(g_tbl[(2 * H + jA) * V + tk1] + r1 * (an1 + bhn));
                float h1 = (1.f - z1) * n1 + z1 * hs1;
                stcg(&hout[jA * B + b0], h0);
                stcg(&hout[jA * B + b1], h1);
                sH4[jlA * 128 + b0] = h0;
                sH4[jlA * 128 + b1] = h1;
            }
            __syncthreads();
            if (tid == 0) d_arrive(PH_H, cta, (unsigned)(t + 1));   // A may start
            {   // p partials: pp[cta][b][d] = sum_jl mW4[jl][d]*h4[jl][b]
                int b2 = tid >> 2, dq = (tid & 3) * 32;
                float h0 = sH4[b2], h1 = sH4[128 + b2];
                float h2 = sH4[256 + b2], h3 = sH4[384 + b2];
                float* dst = &g_pp[((size_t)cta * B + b2) * UD + dq];
#pragma unroll
                for (int dd = 0; dd < 32; dd += 4) {
                    float4 w0 = *(const float4*)(sMW4 + dq + dd);
                    float4 w1 = *(const float4*)(sMW4 + 128 + dq + dd);
                    float4 w2 = *(const float4*)(sMW4 + 256 + dq + dd);
                    float4 w3 = *(const float4*)(sMW4 + 384 + dq + dd);
                    float4 rv;
                    rv.x = w0.x * h0 + w1.x * h1 + w2.x * h2 + w3.x * h3;
                    rv.y = w0.y * h0 + w1.y * h1 + w2.y * h2 + w3.y * h3;
                    rv.z = w0.z * h0 + w1.z * h1 + w2.z * h2 + w3.z * h3;
                    rv.w = w0.w * h0 + w1.w * h1 + w2.w * h2 + w3.w * h3;
                    stcg4(dst + dd, rv);
                }
            }
            if (tid < 128) {
                float s = sMB4[0] * sH4[tid] + sMB4[1] * sH4[128 + tid]
                        + sMB4[2] * sH4[256 + tid] + sMB4[3] * sH4[384 + tid];
                stcg(&g_spp[cta * B + tid], s);
            }
            __syncthreads();
            if (tid == 0) d_arrive(PH_P, cta, (unsigned)(t + 1));   // B may start
        }
    }
}

// ---------------- launch -----------------------------------------------------
extern "C" void kernel_launch(void* const* d_in, const int* in_sizes, int n_in,
                              void* d_out, int out_size) {
    const float* latent = (const float*)d_in[0];
    const float* u      = (const float*)d_in[1];
    const float* embed  = (const float*)d_in[3];
    const float* hid_W  = (const float*)d_in[4];
    const float* hid_b  = (const float*)d_in[5];
    const float* mem_W  = (const float*)d_in[6];
    const float* mem_b  = (const float*)d_in[7];
    const float* W_ih   = (const float*)d_in[8];
    const float* W_hh   = (const float*)d_in[9];
    const float* b_ih   = (const float*)d_in[10];
    const float* b_hh   = (const float*)d_in[11];
    const float* cat_W  = (const float*)d_in[12];
    const float* cat_b  = (const float*)d_in[13];
    const float* out_W  = (const float*)d_in[14];
    const float* out_b  = (const float*)d_in[15];
    float* out = (float*)d_out;

    cudaFuncSetAttribute(decoder_kernel,
                         cudaFuncAttributeMaxDynamicSharedMemorySize, SMEM_BYTES);

    prep_all<<<H3 + 2 * H + 1, 128>>>(embed, W_ih, b_ih, latent, hid_W, hid_b,
                                      cat_W, mem_W, mem_b, cat_b);
    decoder_kernel<<<NCTA, NT, SMEM_BYTES>>>(u, W_hh, b_hh, mem_W, mem_b,
                                             cat_W, out_W, out_b, out);
}

// round 16
// speedup vs baseline: 1.1178x; 1.0545x over previous
#include <cuda_runtime.h>
#include <math.h>
#include <stdint.h>

#define B   128
#define L   500
#define H   512
#define LD  256
#define UD  128
#define V   33
#define H3  1536
#define NCTA 128
#define NT   1024

// dynamic smem float offsets
#define SO_W     0        // 12x512 W_hh (r,z,n x 4 j)
#define SO_CATH  6144     // 4x512 cat_W h-half rows
#define SO_CATM  8192     // 4x128 catM rows
#define SO_MW4   8704     // 4x128 mem_W rows (own 4 j)
#define SO_MB4   9216     // 4 (+pad)
#define SO_OUTW  9232     // 4x34 (+pad)
#define SO_CC    9376     // 4x128 cc
#define SO_H4    9888     // 4x128 h_new own j
#define SO_SB    10400    // 16384: A staging double buffer / finish scratch
#define SO_SBB   26784    // 3104: B-group scratch (16-warp layout)
#define SMEM_FLOATS 29888
#define SMEM_BYTES  (SMEM_FLOATS * 4)

#define PH_H   0
#define PH_Q   1
#define PH_PL  2
#define PH_TOK 3
#define PH_P   4

// ---------------- device scratch ---------------------------------------------
__device__ __align__(16) float g_tbl[H3 * V];
__device__ __align__(16) float g_h[2][H * B];        // [j][b] ping-pong
__device__ __align__(16) float g_qs[UD * B];         // [d][b]
__device__ __align__(16) float g_plog[NCTA * V * B]; // [cta][v][b]
__device__ __align__(16) float g_pp[(size_t)NCTA * B * UD]; // [c][b][d]
__device__ __align__(16) float g_spp[NCTA * B];      // [c][b]
__device__ __align__(16) float g_catM[H * UD];
__device__ float g_catb2[H];
__device__ int g_tok[B];
__device__ __align__(128) unsigned g_flagsD[5][NCTA][8];

// ---------------- helpers ----------------------------------------------------
__device__ __forceinline__ float ldcg(const float* p) {
    float v; asm volatile("ld.global.cg.f32 %0, [%1];" : "=f"(v) : "l"(p)); return v;
}
__device__ __forceinline__ void stcg(float* p, float v) {
    asm volatile("st.global.cg.f32 [%0], %1;" :: "l"(p), "f"(v));
}
__device__ __forceinline__ void stcg4(float* p, float4 v) {
    asm volatile("st.global.cg.v4.f32 [%0], {%1,%2,%3,%4};"
                 :: "l"(p), "f"(v.x), "f"(v.y), "f"(v.z), "f"(v.w));
}
__device__ __forceinline__ float4 ldcg4(const float4* p) {
    float4 v;
    asm volatile("ld.global.cg.v4.f32 {%0,%1,%2,%3}, [%4];"
                 : "=f"(v.x), "=f"(v.y), "=f"(v.z), "=f"(v.w) : "l"(p));
    return v;
}
__device__ __forceinline__ int ldcg_i(const int* p) {
    int v; asm volatile("ld.global.cg.s32 %0, [%1];" : "=r"(v) : "l"(p)); return v;
}
__device__ __forceinline__ void stcg_i(int* p, int v) {
    asm volatile("st.global.cg.s32 [%0], %1;" :: "l"(p), "r"(v));
}
__device__ __forceinline__ void d_arrive(int ph, int cta, unsigned val) {
    asm volatile("st.release.gpu.global.u32 [%0], %1;"
                 :: "l"(&g_flagsD[ph][cta][0]), "r"(val) : "memory");
}
__device__ __forceinline__ void d_poll(int ph, int idx, unsigned val) {
    const unsigned* f = &g_flagsD[ph][idx][0];
    unsigned cur;
    do {
        asm volatile("ld.acquire.gpu.global.u32 %0, [%1];"
                     : "=r"(cur) : "l"(f) : "memory");
    } while ((int)(cur - val) < 0);
}
__device__ __forceinline__ void d_wait(int ph, int tid, unsigned val) {
    if (tid < NCTA) d_poll(ph, tid, val);
    __syncthreads();
}
#define BARA() asm volatile("bar.sync 2, 512;" ::: "memory")
#define BARB() asm volatile("bar.sync 1, 512;" ::: "memory")
__device__ __forceinline__ void cpa16(uint32_t dst, const void* src) {
    asm volatile("cp.async.cg.shared.global [%0], [%1], 16;" :: "r"(dst), "l"(src));
}
__device__ __forceinline__ void cpa_commit() { asm volatile("cp.async.commit_group;"); }
__device__ __forceinline__ void cpa_wait1() { asm volatile("cp.async.wait_group 1;"); }
__device__ __forceinline__ void cpa_wait0() { asm volatile("cp.async.wait_group 0;"); }
__device__ __forceinline__ float sigf(float x) { return 1.f / (1.f + expf(-x)); }

// ---------------- single merged prep kernel ----------------------------------
__global__ void prep_all(const float* __restrict__ embed,
                         const float* __restrict__ W_ih,
                         const float* __restrict__ b_ih,
                         const float* __restrict__ latent,
                         const float* __restrict__ hid_W,
                         const float* __restrict__ hid_b,
                         const float* __restrict__ cat_W,
                         const float* __restrict__ mem_W,
                         const float* __restrict__ mem_b,
                         const float* __restrict__ cat_b) {
    int blk = blockIdx.x, tx = threadIdx.x;
    if (blk < H3) {
        if (tx >= V) return;
        const float* wr = W_ih + (size_t)blk * H;
        const float* er = embed + (size_t)tx * H;
        float acc = b_ih[blk];
#pragma unroll 4
        for (int k = 0; k < H; ++k) acc += er[k] * wr[k];
        g_tbl[blk * V + tx] = acc;
    } else if (blk < H3 + H) {
        int j = blk - H3;
        const float* wr = hid_W + (size_t)j * LD;
        const float* lt = latent + (size_t)tx * LD;
        float acc = hid_b[j];
#pragma unroll 4
        for (int k = 0; k < LD; ++k) acc += lt[k] * wr[k];
        g_h[0][j * B + tx] = acc;
    } else if (blk < H3 + 2 * H) {
        int j = blk - H3 - H;
        const float* cw = cat_W + (size_t)j * (2 * H) + H;
        float acc = 0.f;
#pragma unroll 4
        for (int k = 0; k < H; ++k) acc += cw[k] * mem_W[k * UD + tx];
        g_catM[j * UD + tx] = acc;
        if (tx == 0) {
            float s = cat_b[j];
            for (int k = 0; k < H; ++k) s += cw[k] * mem_b[k];
            g_catb2[j] = s;
        }
    } else {
        if (tx < NCTA) {
#pragma unroll
            for (int p = 0; p < 5; ++p) g_flagsD[p][tx][0] = 0u;
            g_tok[tx] = 0;
        }
    }
}

// ---------------- main persistent decoder ------------------------------------
__global__ void __launch_bounds__(NT, 1)
decoder_kernel(const float* __restrict__ u,
               const float* __restrict__ W_hh,
               const float* __restrict__ b_hh,
               const float* __restrict__ mem_W,
               const float* __restrict__ mem_b,
               const float* __restrict__ cat_W,
               const float* __restrict__ out_W,
               const float* __restrict__ out_b,
               float* __restrict__ out)
{
    extern __shared__ float DS[];
    float* sW    = DS + SO_W;
    float* sCatH = DS + SO_CATH;
    float* sCatM = DS + SO_CATM;
    float* sMW4  = DS + SO_MW4;
    float* sMB4  = DS + SO_MB4;
    float* sOutW = DS + SO_OUTW;
    float* sCC   = DS + SO_CC;
    float* sH4   = DS + SO_H4;
    float* SB    = DS + SO_SB;
    float* SBB   = DS + SO_SBB;
    const uint32_t sbAddr = (uint32_t)__cvta_generic_to_shared(SB);

    const int tid = threadIdx.x;
    const int cta = blockIdx.x;
    const int jc  = cta * 4;

    // ---- persistent weight loads ----
    for (int i = tid; i < 6144; i += NT) {
        int r = i >> 9, k = i & 511;
        sW[i] = W_hh[(size_t)((r >> 2) * H + jc + (r & 3)) * H + k];
    }
    for (int i = tid; i < 2048; i += NT)
        sCatH[i] = cat_W[(size_t)(jc + (i >> 9)) * (2 * H) + (i & 511)];
    for (int i = tid; i < 512; i += NT)
        sCatM[i] = g_catM[(jc + (i >> 7)) * UD + (i & 127)];
    for (int i = tid; i < 512; i += NT)
        sMW4[i] = mem_W[(size_t)(jc + (i >> 7)) * UD + (i & 127)];
    if (tid < 4) sMB4[tid] = mem_b[jc + tid];
    for (int i = tid; i < 4 * V; i += NT) {
        int jl_ = i / V, v_ = i % V;
        sOutW[jl_ * 34 + v_] = out_W[(size_t)v_ * H + jc + jl_];
    }
    __syncthreads();

    // thread identifiers
    const int ta  = tid;                // A-group index (valid tid<512)
    const int kq  = ta >> 7;            // k-quarter within chunk (0..3, A GEMM)
    const int jp  = (ta >> 6) & 1;      // j-pair (A GEMM)
    const int bp2 = ta & 63;            // b-pair (A GEMM)
    const int jlA = (ta >> 6) & 3;      // post-reduction j (valid ta<256)
    const int bp  = ta & 63;
    const int jA  = jc + jlA;
    const float bhr = b_hh[jA], bhz = b_hh[H + jA], bhn = b_hh[2 * H + jA];
    const float ccb = g_catb2[jA];
    const float* wmp = sCatM + jlA * 128;
    const float* wR0 = sW + (0 * 4 + 2 * jp) * 512;
    const float* wR1 = wR0 + 512;
    const float* wZ0 = sW + (1 * 4 + 2 * jp) * 512;
    const float* wZ1 = wZ0 + 512;
    const float* wN0 = sW + (2 * 4 + 2 * jp) * 512;
    const float* wN1 = wN0 + 512;
    const float* wC0 = sCatH + 2 * jp * 512;
    const float* wC1 = wC0 + 512;
    const int tb = tid - 512;           // B-group index (valid tid>=512)

    // live-across-phases registers (meaningful for ta<256)
    float ar0, ar1, az0, az1, an0, an1, ac0, ac1, hs0, hs1;

    for (int t = 0; t <= L; ++t) {
        const float* hin = g_h[t & 1];
        float* hout = g_h[(t + 1) & 1];

        // ================= SPLIT: A (warps 0-15) ∥ B (warps 16-31) ==========
        if (tid < 512) {
            // group-local wait: hout(t-1) stores visible (PH_H)
            if (t > 0 && ta < NCTA) d_poll(PH_H, ta, (unsigned)t);
            BARA();
            // ---- A: gates(t) + cch(t-1); 2j x 2b x k-quarter blocking -------
            float acc[4][2][2];
#pragma unroll
            for (int s = 0; s < 4; ++s)
#pragma unroll
                for (int jj = 0; jj < 2; ++jj) { acc[s][jj][0] = 0.f; acc[s][jj][1] = 0.f; }
            hs0 = hs1 = 0.f;
            {
                const float4* s0 = (const float4*)hin;
#pragma unroll
                for (int i = 0; i < 4; ++i) {
                    int idx = ta + i * 512;
                    cpa16(sbAddr + idx * 16, s0 + idx);
                }
                cpa_commit();
            }
#pragma unroll 1
            for (int c = 0; c < 8; ++c) {
                if (c + 1 < 8) {
                    const float4* s = (const float4*)(hin + (c + 1) * 8192);
                    uint32_t d0 = sbAddr + ((c + 1) & 1) * 32768;
#pragma unroll
                    for (int i = 0; i < 4; ++i) {
                        int idx = ta + i * 512;
                        cpa16(d0 + idx * 16, s + idx);
                    }
                    cpa_commit();
                    cpa_wait1();
                } else {
                    cpa_wait0();
                }
                BARA();
                const float* hbase = SB + (c & 1) * 8192;
                const float* hc = hbase + (kq * 16) * B;
                const int kb = c * 64 + kq * 16;
#pragma unroll
                for (int kk = 0; kk < 16; kk += 4) {
                    float4 r0 = *(const float4*)(wR0 + kb + kk);
                    float4 r1 = *(const float4*)(wR1 + kb + kk);
                    float4 z0 = *(const float4*)(wZ0 + kb + kk);
                    float4 z1 = *(const float4*)(wZ1 + kb + kk);
                    float4 n0 = *(const float4*)(wN0 + kb + kk);
                    float4 n1 = *(const float4*)(wN1 + kb + kk);
                    float4 c0 = *(const float4*)(wC0 + kb + kk);
                    float4 c1 = *(const float4*)(wC1 + kb + kk);
#pragma unroll
                    for (int q = 0; q < 4; ++q) {
                        float2 hv = *(const float2*)(hc + (kk + q) * B + bp2 * 2);
                        float w;
                        w = ((const float*)&r0)[q];
                        acc[0][0][0] += w * hv.x; acc[0][0][1] += w * hv.y;
                        w = ((const float*)&r1)[q];
                        acc[0][1][0] += w * hv.x; acc[0][1][1] += w * hv.y;
                        w = ((const float*)&z0)[q];
                        acc[1][0][0] += w * hv.x; acc[1][0][1] += w * hv.y;
                        w = ((const float*)&z1)[q];
                        acc[1][1][0] += w * hv.x; acc[1][1][1] += w * hv.y;
                        w = ((const float*)&n0)[q];
                        acc[2][0][0] += w * hv.x; acc[2][0][1] += w * hv.y;
                        w = ((const float*)&n1)[q];
                        acc[2][1][0] += w * hv.x; acc[2][1][1] += w * hv.y;
                        w = ((const float*)&c0)[q];
                        acc[3][0][0] += w * hv.x; acc[3][0][1] += w * hv.y;
                        w = ((const float*)&c1)[q];
                        acc[3][1][0] += w * hv.x; acc[3][1][1] += w * hv.y;
                    }
                }
                if (ta < 256 && c == (jA >> 6)) {   // harvest h_self
                    float2 hv = *(const float2*)(hbase + (jA & 63) * B + bp * 2);
                    hs0 = hv.x; hs1 = hv.y;
                }
                BARA();
            }
            // ---- k-quarter reduction: partials -> SMEM -> registers ---------
#pragma unroll
            for (int s = 0; s < 4; ++s)
#pragma unroll
                for (int jj = 0; jj < 2; ++jj)
                    *(float2*)(SB + ((kq * 4 + s) * 4 + 2 * jp + jj) * 128 + bp2 * 2)
                        = make_float2(acc[s][jj][0], acc[s][jj][1]);
            BARA();
            if (ta < 256) {
                ar0 = ar1 = az0 = az1 = an0 = an1 = ac0 = ac1 = 0.f;
#pragma unroll
                for (int set = 0; set < 4; ++set) {
                    float2 v;
                    v = *(const float2*)(SB + ((set * 4 + 0) * 4 + jlA) * 128 + bp * 2);
                    ar0 += v.x; ar1 += v.y;
                    v = *(const float2*)(SB + ((set * 4 + 1) * 4 + jlA) * 128 + bp * 2);
                    az0 += v.x; az1 += v.y;
                    v = *(const float2*)(SB + ((set * 4 + 2) * 4 + jlA) * 128 + bp * 2);
                    an0 += v.x; an1 += v.y;
                    v = *(const float2*)(SB + ((set * 4 + 3) * 4 + jlA) * 128 + bp * 2);
                    ac0 += v.x; ac1 += v.y;
                }
            }
            BARA();   // partial area dead before SB reused
        } else {
            // group-local wait: p-partials visible (PH_P)
            if (t > 0 && tb < NCTA) d_poll(PH_P, tb, (unsigned)t);
            BARB();
            if (t >= 1) {
                // ---- B: attention for b=cta (16 warps), producing qs(t-1) ---
                const int b = cta;
                {   // p[d] quarter-sums over 128 c
                    int d = tb & 127, qtr = tb >> 7;
                    float acc = 0.f;
                    const float* src = &g_pp[((size_t)(qtr * 32) * B + b) * UD + d];
#pragma unroll 8
                    for (int i = 0; i < 32; ++i)
                        acc += ldcg(src + (size_t)i * B * UD);
                    SBB[qtr * 128 + d] = acc;
                }
                if (tb < 32) {  // sbias
                    float s = 0.f;
#pragma unroll
                    for (int k = 0; k < 4; ++k)
                        s += ldcg(&g_spp[(tb * 4 + k) * B + b]);
#pragma unroll
                    for (int o = 16; o > 0; o >>= 1) s += __shfl_xor_sync(~0u, s, o);
                    if (tb == 0) SBB[689] = s;
                }
                BARB();
                if (tb < 128)
                    SBB[512 + tb] = SBB[tb] + SBB[128 + tb] + SBB[256 + tb] + SBB[384 + tb];
                BARB();
                const float sbias = SBB[689];
                const int lane = tb & 31, wb = tb >> 5;   // wb 0..15
                float4 pv = *(const float4*)(SBB + 512 + lane * 4);
                const float* ub = u + (size_t)b * (L * UD) + lane * 4;
                float m0 = -1e30f, Z0 = 0.f, m1 = -1e30f, Z1 = 0.f;
                float4 q0 = {0, 0, 0, 0}, q1 = {0, 0, 0, 0};
                float4 nu0 = ldcg4((const float4*)(ub + (size_t)wb * UD));
                float4 nu1 = (wb + 16 < L) ? ldcg4((const float4*)(ub + (size_t)(wb + 16) * UD))
                                           : make_float4(0, 0, 0, 0);
#pragma unroll 1
                for (int l0 = wb; l0 < L; l0 += 32) {
                    float4 u0 = nu0, u1 = nu1;
                    int l1 = l0 + 16;
                    int n0 = l0 + 32, n1 = l0 + 48;
                    if (n0 < L) {
                        nu0 = ldcg4((const float4*)(ub + (size_t)n0 * UD));
                        nu1 = (n1 < L) ? ldcg4((const float4*)(ub + (size_t)n1 * UD))
                                       : make_float4(0, 0, 0, 0);
                    }
                    float s0v = u0.x * pv.x + u0.y * pv.y + u0.z * pv.z + u0.w * pv.w;
                    float s1v = u1.x * pv.x + u1.y * pv.y + u1.z * pv.z + u1.w * pv.w;
#pragma unroll
                    for (int o = 16; o > 0; o >>= 1) {
                        s0v += __shfl_xor_sync(~0u, s0v, o);
                        s1v += __shfl_xor_sync(~0u, s1v, o);
                    }
                    s0v += sbias; s1v += sbias;
                    if (s0v > m0) {
                        float sc = expf(m0 - s0v);
                        Z0 = Z0 * sc + 1.f;
                        q0.x = q0.x * sc + u0.x; q0.y = q0.y * sc + u0.y;
                        q0.z = q0.z * sc + u0.z; q0.w = q0.w * sc + u0.w;
                        m0 = s0v;
                    } else {
                        float wt = expf(s0v - m0);
                        Z0 += wt;
                        q0.x += wt * u0.x; q0.y += wt * u0.y;
                        q0.z += wt * u0.z; q0.w += wt * u0.w;
                    }
                    if (l1 < L) {
                        if (s1v > m1) {
                            float sc = expf(m1 - s1v);
                            Z1 = Z1 * sc + 1.f;
                            q1.x = q1.x * sc + u1.x; q1.y = q1.y * sc + u1.y;
                            q1.z = q1.z * sc + u1.z; q1.w = q1.w * sc + u1.w;
                            m1 = s1v;
                        } else {
                            float wt = expf(s1v - m1);
                            Z1 += wt;
                            q1.x += wt * u1.x; q1.y += wt * u1.y;
                            q1.z += wt * u1.z; q1.w += wt * u1.w;
                        }
                    }
                }
                {
                    float mn = fmaxf(m0, m1);
                    float sc0 = expf(m0 - mn), sc1 = expf(m1 - mn);
                    Z0 = Z0 * sc0 + Z1 * sc1;
                    q0.x = q0.x * sc0 + q1.x * sc1; q0.y = q0.y * sc0 + q1.y * sc1;
                    q0.z = q0.z * sc0 + q1.z * sc1; q0.w = q0.w * sc0 + q1.w * sc1;
                    m0 = mn;
                }
                *(float4*)(SBB + 1024 + wb * 128 + lane * 4) = q0;
                if (lane == 0) { SBB[640 + wb] = m0; SBB[656 + wb] = Z0; }
                BARB();
                if (tb == 0) {
                    float M = SBB[640];
                    for (int i = 1; i < 16; ++i) M = fmaxf(M, SBB[640 + i]);
                    float Zt = 0.f;
#pragma unroll
                    for (int i = 0; i < 16; ++i) {
                        float e = expf(SBB[640 + i] - M);
                        SBB[672 + i] = e;
                        Zt += e * SBB[656 + i];
                    }
                    SBB[688] = 1.f / Zt;
                }
                BARB();
                if (tb < 128) {
                    float acc = 0.f;
#pragma unroll
                    for (int i = 0; i < 16; ++i)
                        acc += SBB[672 + i] * SBB[1024 + i * 128 + tb];
                    stcg(&g_qs[tb * B + b], acc * SBB[688]);
                }
                BARB();
                if (tb == 0) d_arrive(PH_Q, cta, (unsigned)t);
            }
        }
        __syncthreads();   // join A and B

        // ================= finish step t-1 ==================================
        if (t > 0) {
            d_wait(PH_Q, tid, (unsigned)t);
            {   // stage FULL qs [d][b]: 4096 float4
                const float4* s = (const float4*)g_qs;
                uint32_t d0 = sbAddr;
#pragma unroll
                for (int i = 0; i < 4; ++i) {
                    int idx = tid + i * NT;
                    cpa16(d0 + idx * 16, s + idx);
                }
                cpa_commit();
                cpa_wait0();
            }
            __syncthreads();
            if (tid < 256) {   // cc for b-pair
                float a0 = 0.f, a1 = 0.f;
#pragma unroll
                for (int d = 0; d < UD; d += 4) {
                    float4 w4 = *(const float4*)(wmp + d);
                    float2 v0 = *(const float2*)(SB + d * B + bp * 2);
                    float2 v1 = *(const float2*)(SB + (d + 1) * B + bp * 2);
                    float2 v2 = *(const float2*)(SB + (d + 2) * B + bp * 2);
                    float2 v3 = *(const float2*)(SB + (d + 3) * B + bp * 2);
                    a0 += w4.x * v0.x + w4.y * v1.x + w4.z * v2.x + w4.w * v3.x;
                    a1 += w4.x * v0.y + w4.y * v1.y + w4.z * v2.y + w4.w * v3.y;
                }
                sCC[jlA * 128 + bp * 2]     = tanhf(ac0 + a0 + ccb);
                sCC[jlA * 128 + bp * 2 + 1] = tanhf(ac1 + a1 + ccb);
            }
            __syncthreads();
            {   // partial logits over own 4 j's, all b (8 v-groups)
                int vg = tid >> 7, b2 = tid & 127;
#pragma unroll
                for (int i = 0; i < 5; ++i) {
                    int v = vg + 8 * i;
                    if (v < V) {
                        float a = sOutW[v] * sCC[b2]
                                + sOutW[34 + v] * sCC[128 + b2]
                                + sOutW[68 + v] * sCC[256 + b2]
                                + sOutW[102 + v] * sCC[384 + b2];
                        stcg(&g_plog[((size_t)cta * V + v) * B + b2], a);
                    }
                }
            }
            __syncthreads();
            if (tid == 0) d_arrive(PH_PL, cta, (unsigned)t);
            d_wait(PH_PL, tid, (unsigned)t);
            {   // reduce logits for b=cta (16 groups x 8 c), argmax
                const int b = cta;
                int cg = tid >> 6, v = tid & 63;
                if (v < V) {
                    float acc = 0.f;
#pragma unroll
                    for (int i = 0; i < 8; ++i)
                        acc += ldcg(&g_plog[((size_t)(cg * 8 + i) * V + v) * B + b]);
                    SB[4800 + cg * 64 + v] = acc;
                }
                __syncthreads();
                if (tid < V) {
                    float lg = out_b[tid];
#pragma unroll
                    for (int g = 0; g < 16; ++g) lg += SB[4800 + g * 64 + tid];
                    out[((size_t)b * V + tid) * L + (t - 1)] = lg;
                    SB[5900 + tid] = lg;
                }
                __syncthreads();
                if (t < L && tid < 32) {   // butterfly argmax, first-occurrence
                    float v0 = (tid < V) ? SB[5900 + tid] : -3.4e38f;
                    int i0 = tid;
                    if (tid == 0) {
                        float v32 = SB[5900 + 32];
                        if (v32 > v0) { v0 = v32; i0 = 32; }
                    }
#pragma unroll
                    for (int o = 16; o > 0; o >>= 1) {
                        float ov = __shfl_xor_sync(~0u, v0, o);
                        int oi = __shfl_xor_sync(~0u, i0, o);
                        if (ov > v0 || (ov == v0 && oi < i0)) { v0 = ov; i0 = oi; }
                    }
                    if (tid == 0) {
                        stcg_i(&g_tok[b], i0);
                        d_arrive(PH_TOK, cta, (unsigned)t);
                    }
                }
                __syncthreads();   // protect SB[5900..] until argmax done
            }
        }

        // ================= epilogue: h state + p-partials ===================
        if (t < L) {
            if (t > 0) d_wait(PH_TOK, tid, (unsigned)t);
            if (tid < 256) {
                int b0 = bp * 2, b1 = b0 + 1;
                int tk0 = (t == 0) ? 0 : ldcg_i(&g_tok[b0]);
                int tk1 = (t == 0) ? 0 : ldcg_i(&g_tok[b1]);
                float r0 = sigf(g_tbl[jA * V + tk0] + ar0 + bhr);
                float z0 = sigf(g_tbl[(H + jA) * V + tk0] + az0 + bhz);
                float n0 = tanhf(g_tbl[(2 * H + jA) * V + tk0] + r0 * (an0 + bhn));
                float h0 = (1.f - z0) * n0 + z0 * hs0;
                float r1 = sigf(g_tbl[jA * V + tk1] + ar1 + bhr);
                float z1 = sigf(g_tbl[(H + jA) * V + tk1] + az1 + bhz);
                float n1 = tanhf(g_tbl[(2 * H + jA) * V + tk1] + r1 * (an1 + bhn));
                float h1 = (1.f - z1) * n1 + z1 * hs1;
                stcg(&hout[jA * B + b0], h0);
                stcg(&hout[jA * B + b1], h1);
                sH4[jlA * 128 + b0] = h0;
                sH4[jlA * 128 + b1] = h1;
            }
            __syncthreads();
            if (tid == 0) d_arrive(PH_H, cta, (unsigned)(t + 1));   // A may start
            {   // p partials: pp[cta][b][d] = sum_jl mW4[jl][d]*h4[jl][b]
                int b2 = tid >> 3, dq = (tid & 7) * 16;
                float h0 = sH4[b2], h1 = sH4[128 + b2];
                float h2 = sH4[256 + b2], h3 = sH4[384 + b2];
                float* dst = &g_pp[((size_t)cta * B + b2) * UD + dq];
#pragma unroll
                for (int dd = 0; dd < 16; dd += 4) {
                    float4 w0 = *(const float4*)(sMW4 + dq + dd);
                    float4 w1 = *(const float4*)(sMW4 + 128 + dq + dd);
                    float4 w2 = *(const float4*)(sMW4 + 256 + dq + dd);
                    float4 w3 = *(const float4*)(sMW4 + 384 + dq + dd);
                    float4 rv;
                    rv.x = w0.x * h0 + w1.x * h1 + w2.x * h2 + w3.x * h3;
                    rv.y = w0.y * h0 + w1.y * h1 + w2.y * h2 + w3.y * h3;
                    rv.z = w0.z * h0 + w1.z * h1 + w2.z * h2 + w3.z * h3;
                    rv.w = w0.w * h0 + w1.w * h1 + w2.w * h2 + w3.w * h3;
                    stcg4(dst + dd, rv);
                }
            }
            if (tid < 128) {
                float s = sMB4[0] * sH4[tid] + sMB4[1] * sH4[128 + tid]
                        + sMB4[2] * sH4[256 + tid] + sMB4[3] * sH4[384 + tid];
                stcg(&g_spp[cta * B + tid], s);
            }
            __syncthreads();
            if (tid == 0) d_arrive(PH_P, cta, (unsigned)(t + 1));   // B may start
        }
    }
}

// ---------------- launch -----------------------------------------------------
extern "C" void kernel_launch(void* const* d_in, const int* in_sizes, int n_in,
                              void* d_out, int out_size) {
    const float* latent = (const float*)d_in[0];
    const float* u      = (const float*)d_in[1];
    const float* embed  = (const float*)d_in[3];
    const float* hid_W  = (const float*)d_in[4];
    const float* hid_b  = (const float*)d_in[5];
    const float* mem_W  = (const float*)d_in[6];
    const float* mem_b  = (const float*)d_in[7];
    const float* W_ih   = (const float*)d_in[8];
    const float* W_hh   = (const float*)d_in[9];
    const float* b_ih   = (const float*)d_in[10];
    const float* b_hh   = (const float*)d_in[11];
    const float* cat_W  = (const float*)d_in[12];
    const float* cat_b  = (const float*)d_in[13];
    const float* out_W  = (const float*)d_in[14];
    const float* out_b  = (const float*)d_in[15];
    float* out = (float*)d_out;

    cudaFuncSetAttribute(decoder_kernel,
                         cudaFuncAttributeMaxDynamicSharedMemorySize, SMEM_BYTES);

    prep_all<<<H3 + 2 * H + 1, 128>>>(embed, W_ih, b_ih, latent, hid_W, hid_b,
                                      cat_W, mem_W, mem_b, cat_b);
    decoder_kernel<<<NCTA, NT, SMEM_BYTES>>>(u, W_hh, b_hh, mem_W, mem_b,
                                             cat_W, out_W, out_b, out);
}